// round 1
// baseline (speedup 1.0000x reference)
#include <cuda_runtime.h>
#include <cstdint>

// ===========================================================================
// reinforce_cons_loss — full pipeline:
//   K0 reset seeds
//   K1 Threefry-2x32 Gumbel-max categorical sampling (JAX partitionable mode)
//   K2 5x5 fg-neighbor counts + per-(task,class) argmax seed (packed byte-SIMD)
//   K3 per-(task,class) 8-connectivity flood fill (bitset dilation in SMEM)
//      + sum of log(p_sampled + eps) over component pixels
//   K4 final scalar loss
// ===========================================================================

// ---- RNG mode switches (round-2 fallbacks if rel_err is large) ------------
// 1 = jax_threefry_partitionable (default in modern JAX): counter=(0,i), out=o0^o1
// 0 = legacy mode: iota split into halves, out = o0 for i<half else o1
#define TF_PARTITIONABLE 1
// In partitionable mode: 1 -> bits = o0^o1 ; 0 -> bits = o0
#define TF_XOR 1

#define NIMG   4
#define NSAMP  10
#define HH     512
#define WW     512
#define NTASK  (NIMG*NSAMP)            // 40 image-samples
#define NPIX   (HH*WW)                 // 262144 = 1<<18
#define TOTPIX ((unsigned)NTASK*NPIX)  // 10485760
#define NCLS   4
#define NGUM   (TOTPIX*4u)             // 41943040
#define HALF   (NGUM/2u)

__device__ uint8_t            g_cls[(size_t)NTASK * NPIX];
__device__ unsigned long long g_seed[NTASK * 3];
__device__ double             g_partial[NTASK * 3];

// ---------------------------------------------------------------------------
// Threefry-2x32, 20 rounds (matches jax._src.prng.threefry2x32)
// ---------------------------------------------------------------------------
#define TF_ROUND(x0,x1,R) { x0 += x1; x1 = (x1<<(R))|(x1>>(32-(R))); x1 ^= x0; }

__device__ __forceinline__ void threefry2x32(uint32_t k0, uint32_t k1,
                                             uint32_t x0, uint32_t x1,
                                             uint32_t& o0, uint32_t& o1) {
    uint32_t k2 = k0 ^ k1 ^ 0x1BD11BDAu;
    x0 += k0; x1 += k1;
    TF_ROUND(x0,x1,13) TF_ROUND(x0,x1,15) TF_ROUND(x0,x1,26) TF_ROUND(x0,x1,6)
    x0 += k1; x1 += k2 + 1u;
    TF_ROUND(x0,x1,17) TF_ROUND(x0,x1,29) TF_ROUND(x0,x1,16) TF_ROUND(x0,x1,24)
    x0 += k2; x1 += k0 + 2u;
    TF_ROUND(x0,x1,13) TF_ROUND(x0,x1,15) TF_ROUND(x0,x1,26) TF_ROUND(x0,x1,6)
    x0 += k0; x1 += k1 + 3u;
    TF_ROUND(x0,x1,17) TF_ROUND(x0,x1,29) TF_ROUND(x0,x1,16) TF_ROUND(x0,x1,24)
    x0 += k1; x1 += k2 + 4u;
    TF_ROUND(x0,x1,13) TF_ROUND(x0,x1,15) TF_ROUND(x0,x1,26) TF_ROUND(x0,x1,6)
    x0 += k2; x1 += k0 + 5u;
    o0 = x0; o1 = x1;
}

__device__ __forceinline__ uint32_t gumbel_bits(unsigned idx) {
    uint32_t o0, o1;
#if TF_PARTITIONABLE
    threefry2x32(0u, 42u, 0u, idx, o0, o1);
#if TF_XOR
    return o0 ^ o1;
#else
    return o0;
#endif
#else
    if (idx < HALF) { threefry2x32(0u, 42u, idx, idx + HALF, o0, o1); return o0; }
    else            { threefry2x32(0u, 42u, idx - HALF, idx, o0, o1); return o1; }
#endif
}

// ---------------------------------------------------------------------------
// K0: reset per-launch state
// ---------------------------------------------------------------------------
__global__ void k_reset() {
    int i = threadIdx.x;
    if (i < NTASK * 3) g_seed[i] = 0ull;
}

// ---------------------------------------------------------------------------
// K1: gumbel-max sampling.  gumbel tensor shape (S, n, H, W, C); element index
//     i = pixel*4 + c with pixel = ((s*4+n)<<18)|hw.
//     u = max(tiny, bitcast(bits>>9 | 0x3f800000) - 1);  g = -log(-log(u))
//     class = argmax_c ( g_c + log(preds[n,c,h,w] + 1e-16) )  (first max wins)
// ---------------------------------------------------------------------------
__global__ void __launch_bounds__(256) k_sample(const float* __restrict__ preds) {
    unsigned gid = blockIdx.x * 256u + threadIdx.x;
    if (gid >= TOTPIX) return;
    unsigned hw = gid & 0x3FFFFu;
    unsigned n  = (gid >> 18) & 3u;
    const float* pb = preds + ((size_t)n << 20) + hw;   // preds[n][c][h][w]
    unsigned base = gid << 2;

    float best = -__int_as_float(0x7f800000);
    unsigned bc = 0;
#pragma unroll
    for (unsigned c = 0; c < 4; c++) {
        uint32_t bits = gumbel_bits(base + c);
        float f = __uint_as_float((bits >> 9) | 0x3f800000u) - 1.0f;
        float u = fmaxf(f, 1.17549435082228751e-38f);
        float g = -logf(-logf(u));
        float v = g + logf(pb[(size_t)c << 18] + 1e-16f);
        if (v > best) { best = v; bc = c; }
    }
    g_cls[gid] = (uint8_t)bc;
}

// ---------------------------------------------------------------------------
// K2: per task t (40) and 16-row block (32): 5x5 box counts of each class,
//     packed one class per byte lane of a u32 (counts <= 25). For each fg
//     pixel, candidate key = (count<<18) | (0x3FFFF - flat_idx); global
//     atomicMax => max count, lowest flat index on ties.
// ---------------------------------------------------------------------------
__global__ void __launch_bounds__(256) k_seed() {
    __shared__ uint32_t           scls[20][128];   // class bytes, rows r0-2..r0+17
    __shared__ uint32_t           svs[16][512];    // vertical 5-sums, packed bytes
    __shared__ unsigned long long sbest[3];

    int tid = threadIdx.x;
    int t   = blockIdx.y;
    int r0  = blockIdx.x * 16;
    const uint32_t* cls32 = (const uint32_t*)g_cls + (size_t)t * (NPIX/4);

    for (int i = tid; i < 20 * 128; i += 256) {
        int row = i >> 7, wd = i & 127;
        int rr = r0 - 2 + row;
        scls[row][wd] = (rr >= 0 && rr < HH) ? cls32[rr * 128 + wd] : 0u;
    }
    if (tid < 3) sbest[tid] = 0ull;
    __syncthreads();

    // vertical sliding 5-sums
    for (int x = tid; x < 512; x += 256) {
        int wd = x >> 2, sh = (x & 3) * 8;
        uint32_t w = 0;
#pragma unroll
        for (int k = 0; k < 5; k++) {
            uint32_t b = (scls[k][wd] >> sh) & 0xFFu;
            w += 1u << (b << 3);
        }
        svs[0][x] = w;
        for (int y = 1; y < 16; y++) {
            uint32_t ba = (scls[y + 4][wd] >> sh) & 0xFFu;
            uint32_t bs = (scls[y - 1][wd] >> sh) & 0xFFu;
            w += (1u << (ba << 3)) - (1u << (bs << 3));
            svs[y][x] = w;
        }
    }
    __syncthreads();

    unsigned long long lbest0 = 0, lbest1 = 0, lbest2 = 0;
    for (int i = tid; i < 16 * 512; i += 256) {
        int y = i >> 9, x = i & 511;
        uint32_t c0 = (scls[y + 2][x >> 2] >> ((x & 3) * 8)) & 0xFFu;
        if (c0 == 0u) continue;
        uint32_t h = svs[y][x];
        if (x >= 1)   h += svs[y][x - 1];
        if (x >= 2)   h += svs[y][x - 2];
        if (x <= 510) h += svs[y][x + 1];
        if (x <= 509) h += svs[y][x + 2];
        uint32_t cnt = (h >> (c0 << 3)) & 0xFFu;
        unsigned idx = ((unsigned)(r0 + y) << 9) | (unsigned)x;
        unsigned long long key =
            ((unsigned long long)cnt << 18) | (unsigned long long)(0x3FFFFu - idx);
        if (c0 == 1u)      { if (key > lbest0) lbest0 = key; }
        else if (c0 == 2u) { if (key > lbest1) lbest1 = key; }
        else               { if (key > lbest2) lbest2 = key; }
    }
    if (lbest0) atomicMax(&sbest[0], lbest0);
    if (lbest1) atomicMax(&sbest[1], lbest1);
    if (lbest2) atomicMax(&sbest[2], lbest2);
    __syncthreads();
    if (tid < 3 && sbest[tid]) atomicMax(&g_seed[t * 3 + tid], sbest[tid]);
}

// ---------------------------------------------------------------------------
// K3: one CTA per (task, class). fg + fill as 512x512 bitsets in SMEM.
//     In-place monotone 8-connectivity dilation restricted to a growing row
//     bbox until fixed point == connected component of the seed. Then sum
//     log(preds[n,c,h,w] + 1e-16) over component pixels (deterministic
//     tree reduction, per-CTA partial written to fixed slot).
// ---------------------------------------------------------------------------
__global__ void __launch_bounds__(256) k_flood(const float* __restrict__ preds) {
    extern __shared__ uint32_t sm[];
    uint32_t* fg = sm;          // 8192 words
    uint32_t* fl = sm + 8192;   // 8192 words
    __shared__ int s_r0, s_r1, s_changed;
    __shared__ double s_red[8];

    int tid  = threadIdx.x;
    int task = blockIdx.x;
    int t = task / 3;
    int c = task % 3 + 1;
    int n = t & 3;

    unsigned long long key = g_seed[task];
    if ((key >> 18) == 0ull) {          // empty fg -> zero contribution
        if (tid == 0) g_partial[task] = 0.0;
        return;
    }

    // build fg bitset for class c
    const uint32_t* cls32 = (const uint32_t*)g_cls + (size_t)t * (NPIX/4);
    uint32_t cpat = (uint32_t)c * 0x01010101u;
    for (int w = tid; w < 8192; w += 256) {
        uint32_t bits = 0;
#pragma unroll
        for (int k = 0; k < 8; k++) {
            uint32_t v  = cls32[w * 8 + k];
            uint32_t eq = __vcmpeq4(v, cpat);                      // 0xFF per match
            uint32_t nb = ((eq & 0x01010101u) * 0x01020408u) >> 24; // 4 bits
            bits |= (nb & 0xFu) << (k * 4);
        }
        fg[w] = bits;
        fl[w] = 0u;
    }
    __syncthreads();

    int sidx = 0x3FFFF - (int)(key & 0x3FFFFull);
    if (tid == 0) {
        int sr = sidx >> 9, sc = sidx & 511;
        fl[sr * 16 + (sc >> 5)] = 1u << (sc & 31);
        s_r0 = sr; s_r1 = sr;
    }
    __syncthreads();

    for (int iter = 0; iter < 262200; iter++) {
        if (tid == 0) s_changed = 0;
        __syncthreads();
        int r0 = s_r0 > 0   ? s_r0 - 1 : 0;
        int r1 = s_r1 < 511 ? s_r1 + 1 : 511;
        int ch = 0, myr0 = 1 << 30, myr1 = -1;
        for (int r = r0 + tid; r <= r1; r += 256) {
            uint32_t* F = fl + r * 16;
            const uint32_t* G = fg + r * 16;
            bool hasU = (r > 0), hasD = (r < 511);
            const uint32_t* U = fl + (r - 1) * 16;
            const uint32_t* D = fl + (r + 1) * 16;
            uint32_t Aprev = 0;
            uint32_t Acur = F[0] | (hasU ? U[0] : 0u) | (hasD ? D[0] : 0u);
            bool rowch = false;
#pragma unroll
            for (int j = 0; j < 16; j++) {
                uint32_t Anext = (j < 15)
                    ? (F[j+1] | (hasU ? U[j+1] : 0u) | (hasD ? D[j+1] : 0u)) : 0u;
                uint32_t spread = Acur | (Acur << 1) | (Aprev >> 31)
                                       | (Acur >> 1) | (Anext << 31);
                uint32_t nw = F[j] | (spread & G[j]);
                if (nw != F[j]) { F[j] = nw; rowch = true; }
                Aprev = Acur; Acur = Anext;
            }
            if (rowch) { ch = 1; if (r < myr0) myr0 = r; if (r > myr1) myr1 = r; }
        }
        if (ch) {
            s_changed = 1;
            atomicMin(&s_r0, myr0);
            atomicMax(&s_r1, myr1);
        }
        __syncthreads();
        if (!s_changed) break;
    }

    // sum log(prob + eps) over component pixels
    double acc = 0.0;
    const float* pb = preds + ((size_t)(n * 4 + c) << 18);
    for (int w = tid; w < 8192; w += 256) {
        uint32_t m = fl[w];
        int rowbase = (w >> 4) << 9;
        int colbase = (w & 15) << 5;
        while (m) {
            int b = __ffs(m) - 1;
            m &= m - 1;
            float p = pb[rowbase + colbase + b];
            acc += (double)logf(p + 1e-16f);
        }
    }
    // deterministic reduction
#pragma unroll
    for (int off = 16; off; off >>= 1)
        acc += __shfl_down_sync(0xFFFFFFFFu, acc, off);
    if ((tid & 31) == 0) s_red[tid >> 5] = acc;
    __syncthreads();
    if (tid == 0) {
        double tt = 0.0;
#pragma unroll
        for (int i = 0; i < 8; i++) tt += s_red[i];
        g_partial[task] = tt;
    }
}

// ---------------------------------------------------------------------------
// K4: loss = -(sum of partials) / (n*S*H*W)   (fixed summation order)
// ---------------------------------------------------------------------------
__global__ void k_final(float* __restrict__ out) {
    double s = 0.0;
    for (int i = 0; i < NTASK * 3; i++) s += g_partial[i];
    out[0] = (float)(-s / (double)TOTPIX);
}

// ---------------------------------------------------------------------------
extern "C" void kernel_launch(void* const* d_in, const int* in_sizes, int n_in,
                              void* d_out, int out_size) {
    (void)in_sizes; (void)n_in; (void)out_size;
    const float* preds = (const float*)d_in[0];
    float* out = (float*)d_out;

    cudaFuncSetAttribute(k_flood, cudaFuncAttributeMaxDynamicSharedMemorySize,
                         2 * 8192 * (int)sizeof(uint32_t));

    k_reset<<<1, 128>>>();
    k_sample<<<(TOTPIX + 255) / 256, 256>>>(preds);
    {
        dim3 g(HH / 16, NTASK);
        k_seed<<<g, 256>>>();
    }
    k_flood<<<NTASK * 3, 256, 2 * 8192 * sizeof(uint32_t)>>>(preds);
    k_final<<<1, 1>>>(out);
}

// round 2
// speedup vs baseline: 1.1797x; 1.1797x over previous
#include <cuda_runtime.h>
#include <cstdint>

// ===========================================================================
// reinforce_cons_loss:
//   K1 Threefry-2x32 Gumbel-max categorical sampling (product-form argmax)
//      (+ inline reset of g_seed by block 0)
//   K2 5x5 fg-neighbor counts + per-(task,class) argmax seed (packed byte-SIMD)
//   K3 per-(task,class) 8-connectivity flood fill: bitset rows with FULL
//      horizontal closure per iteration (adder smear + brev), 1 barrier/iter
//      + sum of log(p_sampled + eps) over component pixels
//   K4 final scalar loss
// ===========================================================================

#define NIMG   4
#define NSAMP  10
#define HH     512
#define WW     512
#define NTASK  (NIMG*NSAMP)            // 40 image-samples
#define NPIX   (HH*WW)                 // 262144 = 1<<18
#define TOTPIX ((unsigned)NTASK*NPIX)  // 10485760

__device__ uint8_t            g_cls[(size_t)NTASK * NPIX];
__device__ unsigned long long g_seed[NTASK * 3];
__device__ double             g_partial[NTASK * 3];

// ---------------------------------------------------------------------------
// Threefry-2x32, 20 rounds, key (0,42), counter (0, idx); out = o0 ^ o1
// (jax_threefry_partitionable mode — verified in round 1, rel_err 6e-8)
// ---------------------------------------------------------------------------
#define TF_ROUND(x0,x1,R) { x0 += x1; x1 = __funnelshift_l(x1, x1, (R)); x1 ^= x0; }

__device__ __forceinline__ uint32_t gumbel_bits(uint32_t idx) {
    const uint32_t k0 = 0u, k1 = 42u;
    const uint32_t k2 = k0 ^ k1 ^ 0x1BD11BDAu;
    uint32_t x0 = k0, x1 = idx + k1;
    TF_ROUND(x0,x1,13) TF_ROUND(x0,x1,15) TF_ROUND(x0,x1,26) TF_ROUND(x0,x1,6)
    x0 += k1; x1 += k2 + 1u;
    TF_ROUND(x0,x1,17) TF_ROUND(x0,x1,29) TF_ROUND(x0,x1,16) TF_ROUND(x0,x1,24)
    x0 += k2; x1 += k0 + 2u;
    TF_ROUND(x0,x1,13) TF_ROUND(x0,x1,15) TF_ROUND(x0,x1,26) TF_ROUND(x0,x1,6)
    x0 += k0; x1 += k1 + 3u;
    TF_ROUND(x0,x1,17) TF_ROUND(x0,x1,29) TF_ROUND(x0,x1,16) TF_ROUND(x0,x1,24)
    x0 += k1; x1 += k2 + 4u;
    TF_ROUND(x0,x1,13) TF_ROUND(x0,x1,15) TF_ROUND(x0,x1,26) TF_ROUND(x0,x1,6)
    x0 += k2; x1 += k0 + 5u;
    return x0 ^ x1;
}

// ---------------------------------------------------------------------------
// K1: gumbel-max sampling, product form.
//   u_c = max(tiny, bitcast(bits>>9 | 0x3f800000) - 1)
//   argmax_c ( -log(-log u_c) + log(p_c + eps) )  ==  argmax_c  p_c / (-log2 u_c)
//   (monotone transforms; uniform scale of w cancels in cross-multiplication;
//    eps=1e-16 < ulp(p) so p+eps == p in f32). First-index tie-break kept via
//    strict-> replacement.
// ---------------------------------------------------------------------------
__global__ void __launch_bounds__(256) k_sample(const float* __restrict__ preds) {
    unsigned gid = blockIdx.x * 256u + threadIdx.x;
    if (blockIdx.x == 0 && threadIdx.x < NTASK * 3) g_seed[threadIdx.x] = 0ull;
    if (gid >= TOTPIX) return;
    unsigned hw = gid & 0x3FFFFu;
    unsigned n  = (gid >> 18) & 3u;
    const float* pb = preds + ((size_t)n << 20) + hw;   // preds[n][c][h][w]
    unsigned base = gid << 2;

    float p0 = pb[0];
    float p1 = pb[(size_t)1 << 18];
    float p2 = pb[(size_t)2 << 18];
    float p3 = pb[(size_t)3 << 18];

    const float tiny = 1.17549435082228751e-38f;
    uint32_t b0 = gumbel_bits(base + 0);
    uint32_t b1 = gumbel_bits(base + 1);
    uint32_t b2 = gumbel_bits(base + 2);
    uint32_t b3 = gumbel_bits(base + 3);
    float u0 = fmaxf(__uint_as_float((b0 >> 9) | 0x3f800000u) - 1.0f, tiny);
    float u1 = fmaxf(__uint_as_float((b1 >> 9) | 0x3f800000u) - 1.0f, tiny);
    float u2 = fmaxf(__uint_as_float((b2 >> 9) | 0x3f800000u) - 1.0f, tiny);
    float u3 = fmaxf(__uint_as_float((b3 >> 9) | 0x3f800000u) - 1.0f, tiny);
    float w0 = -log2f(u0);
    float w1 = -log2f(u1);
    float w2 = -log2f(u2);
    float w3 = -log2f(u3);

    float bp = p0, bw = w0; unsigned bc = 0;
    if (p1 * bw > bp * w1) { bp = p1; bw = w1; bc = 1; }
    if (p2 * bw > bp * w2) { bp = p2; bw = w2; bc = 2; }
    if (p3 * bw > bp * w3) { bp = p3; bw = w3; bc = 3; }
    g_cls[gid] = (uint8_t)bc;
}

// ---------------------------------------------------------------------------
// K2: per task t (40) and 16-row block (32): 5x5 box counts of each class,
//     packed one class per byte lane of a u32 (counts <= 25). For each fg
//     pixel, candidate key = (count<<18) | (0x3FFFF - flat_idx); global
//     atomicMax => max count, lowest flat index on ties.
// ---------------------------------------------------------------------------
__global__ void __launch_bounds__(256) k_seed() {
    __shared__ uint32_t           scls[20][128];   // class bytes, rows r0-2..r0+17
    __shared__ uint32_t           svs[16][512];    // vertical 5-sums, packed bytes
    __shared__ unsigned long long sbest[3];

    int tid = threadIdx.x;
    int t   = blockIdx.y;
    int r0  = blockIdx.x * 16;
    const uint32_t* cls32 = (const uint32_t*)g_cls + (size_t)t * (NPIX/4);

    for (int i = tid; i < 20 * 128; i += 256) {
        int row = i >> 7, wd = i & 127;
        int rr = r0 - 2 + row;
        scls[row][wd] = (rr >= 0 && rr < HH) ? cls32[rr * 128 + wd] : 0u;
    }
    if (tid < 3) sbest[tid] = 0ull;
    __syncthreads();

    // vertical sliding 5-sums
    for (int x = tid; x < 512; x += 256) {
        int wd = x >> 2, sh = (x & 3) * 8;
        uint32_t w = 0;
#pragma unroll
        for (int k = 0; k < 5; k++) {
            uint32_t b = (scls[k][wd] >> sh) & 0xFFu;
            w += 1u << (b << 3);
        }
        svs[0][x] = w;
        for (int y = 1; y < 16; y++) {
            uint32_t ba = (scls[y + 4][wd] >> sh) & 0xFFu;
            uint32_t bs = (scls[y - 1][wd] >> sh) & 0xFFu;
            w += (1u << (ba << 3)) - (1u << (bs << 3));
            svs[y][x] = w;
        }
    }
    __syncthreads();

    unsigned long long lbest0 = 0, lbest1 = 0, lbest2 = 0;
    for (int i = tid; i < 16 * 512; i += 256) {
        int y = i >> 9, x = i & 511;
        uint32_t c0 = (scls[y + 2][x >> 2] >> ((x & 3) * 8)) & 0xFFu;
        if (c0 == 0u) continue;
        uint32_t h = svs[y][x];
        if (x >= 1)   h += svs[y][x - 1];
        if (x >= 2)   h += svs[y][x - 2];
        if (x <= 510) h += svs[y][x + 1];
        if (x <= 509) h += svs[y][x + 2];
        uint32_t cnt = (h >> (c0 << 3)) & 0xFFu;
        unsigned idx = ((unsigned)(r0 + y) << 9) | (unsigned)x;
        unsigned long long key =
            ((unsigned long long)cnt << 18) | (unsigned long long)(0x3FFFFu - idx);
        if (c0 == 1u)      { if (key > lbest0) lbest0 = key; }
        else if (c0 == 2u) { if (key > lbest1) lbest1 = key; }
        else               { if (key > lbest2) lbest2 = key; }
    }
    if (lbest0) atomicMax(&sbest[0], lbest0);
    if (lbest1) atomicMax(&sbest[1], lbest1);
    if (lbest2) atomicMax(&sbest[2], lbest2);
    __syncthreads();
    if (tid < 3 && sbest[tid]) atomicMax(&g_seed[t * 3 + tid], sbest[tid]);
}

// ---------------------------------------------------------------------------
// K3: one CTA (128 thr) per (task, class). fg + fill as 512x512 bitsets in
//     SMEM. Each iteration: per-row candidate seeds (vertical+diag neighbors)
//     followed by FULL horizontal closure within the row:
//       within-word: up = G & ~(G+S); down via __brev; two cross-word carry
//       passes (L->R then R->L) give the exact 1-D closure.
//     Converges in ~#vertical-windings iterations. One __syncthreads per
//     iteration via a 3-slot rotating changed-flag.
// ---------------------------------------------------------------------------
__device__ __forceinline__ uint32_t word_closure(uint32_t g, uint32_t s) {
    uint32_t up = g & ~(g + s);
    uint32_t gr = __brev(g), sr = __brev(s);
    uint32_t dn = __brev(gr & ~(gr + sr));
    return s | up | dn;
}

__global__ void __launch_bounds__(128) k_flood(const float* __restrict__ preds) {
    extern __shared__ uint32_t sm[];
    uint32_t* fg = sm;          // 8192 words
    uint32_t* fl = sm + 8192;   // 8192 words
    __shared__ int s_r0, s_r1;
    __shared__ int s_flag[3];
    __shared__ double s_red[4];

    int tid  = threadIdx.x;
    int task = blockIdx.x;
    int t = task / 3;
    int c = task % 3 + 1;
    int n = t & 3;

    unsigned long long key = g_seed[task];
    if ((key >> 18) == 0ull) {          // empty fg -> zero contribution
        if (tid == 0) g_partial[task] = 0.0;
        return;
    }

    // build fg bitset for class c
    const uint32_t* cls32 = (const uint32_t*)g_cls + (size_t)t * (NPIX/4);
    uint32_t cpat = (uint32_t)c * 0x01010101u;
    for (int w = tid; w < 8192; w += 128) {
        uint32_t bits = 0;
#pragma unroll
        for (int k = 0; k < 8; k++) {
            uint32_t v  = cls32[w * 8 + k];
            uint32_t eq = __vcmpeq4(v, cpat);                      // 0xFF per match
            uint32_t nb = ((eq & 0x01010101u) * 0x01020408u) >> 24; // 4 bits
            bits |= (nb & 0xFu) << (k * 4);
        }
        fg[w] = bits;
        fl[w] = 0u;
    }
    if (tid == 0) {
        int sidx = 0x3FFFF - (int)(key & 0x3FFFFull);
        s_r0 = sidx >> 9; s_r1 = sidx >> 9;
        s_flag[0] = 0; s_flag[1] = 0; s_flag[2] = 0;
        // defer seed-bit store until after barrier? No: fl cleared above by all
        // threads before this barrier; store seed here is racy with another
        // thread clearing the same word? Each word cleared exactly once, and
        // thread0 also participates in clearing. Store the seed AFTER barrier.
    }
    __syncthreads();
    if (tid == 0) {
        int sidx = 0x3FFFF - (int)(key & 0x3FFFFull);
        int sr = sidx >> 9, sc = sidx & 511;
        fl[sr * 16 + (sc >> 5)] = 1u << (sc & 31);
    }
    __syncthreads();

    for (int iter = 0; ; iter++) {
        int p = iter % 3;
        int r0 = s_r0 > 0   ? s_r0 - 1 : 0;
        int r1 = s_r1 < 511 ? s_r1 + 1 : 511;
        int ch = 0, myr0 = 1 << 30, myr1 = -1;
        for (int r = r0 + tid; r <= r1; r += 128) {
            uint32_t* F = fl + r * 16;
            const uint32_t* G = fg + r * 16;
            bool hU = (r > 0), hD = (r < 511);
            const uint32_t* U = fl + (r - 1) * 16;
            const uint32_t* D = fl + (r + 1) * 16;
            uint32_t S[16], Gw[16], Fo[16];
            uint32_t Vp = 0;
            uint32_t Vc = (hU ? U[0] : 0u) | (hD ? D[0] : 0u);
#pragma unroll
            for (int j = 0; j < 16; j++) {
                uint32_t Vn = (j < 15)
                    ? ((hU ? U[j+1] : 0u) | (hD ? D[j+1] : 0u)) : 0u;
                Gw[j] = G[j];
                Fo[j] = F[j];
                uint32_t vd = Vc | (Vc << 1) | (Vp >> 31) | (Vc >> 1) | (Vn << 31);
                S[j] = Fo[j] | (vd & Gw[j]);
                Vp = Vc; Vc = Vn;
            }
            // L->R closure pass
            uint32_t carry = 0;
#pragma unroll
            for (int j = 0; j < 16; j++) {
                uint32_t s = S[j] | (carry & Gw[j] & 1u);
                uint32_t cl = word_closure(Gw[j], s);
                S[j] = cl; carry = cl >> 31;
            }
            // R->L closure pass
            carry = 0;
            uint32_t diff = 0;
#pragma unroll
            for (int j = 15; j >= 0; j--) {
                uint32_t s = S[j] | ((0u - carry) & Gw[j] & 0x80000000u);
                uint32_t cl = word_closure(Gw[j], s);
                S[j] = cl; carry = cl & 1u;
                diff |= cl ^ Fo[j];
            }
            if (diff) {
#pragma unroll
                for (int j = 0; j < 16; j++) F[j] = S[j];
                ch = 1; if (r < myr0) myr0 = r; if (r > myr1) myr1 = r;
            }
        }
        if (ch) {
            s_flag[p] = 1;
            atomicMin(&s_r0, myr0);
            atomicMax(&s_r1, myr1);
        }
        if (tid == 0) s_flag[(p + 1) % 3] = 0;   // next slot; readers of it were
        __syncthreads();                          // 2 barriers ago -> ordered
        if (!s_flag[p]) break;
    }

    // sum log(prob + eps) over component pixels
    double acc = 0.0;
    const float* pb = preds + ((size_t)(n * 4 + c) << 18);
    for (int w = tid; w < 8192; w += 128) {
        uint32_t m = fl[w];
        int rowbase = (w >> 4) << 9;
        int colbase = (w & 15) << 5;
        while (m) {
            int b = __ffs(m) - 1;
            m &= m - 1;
            float p = pb[rowbase + colbase + b];
            acc += (double)logf(p + 1e-16f);
        }
    }
#pragma unroll
    for (int off = 16; off; off >>= 1)
        acc += __shfl_down_sync(0xFFFFFFFFu, acc, off);
    if ((tid & 31) == 0) s_red[tid >> 5] = acc;
    __syncthreads();
    if (tid == 0) {
        double tt = 0.0;
#pragma unroll
        for (int i = 0; i < 4; i++) tt += s_red[i];
        g_partial[task] = tt;
    }
}

// ---------------------------------------------------------------------------
// K4: loss = -(sum of partials) / (n*S*H*W)   (fixed deterministic order)
// ---------------------------------------------------------------------------
__global__ void k_final(float* __restrict__ out) {
    __shared__ double sv[NTASK * 3];
    int tid = threadIdx.x;
    if (tid < NTASK * 3) sv[tid] = g_partial[tid];
    __syncthreads();
    if (tid == 0) {
        double s = 0.0;
        for (int i = 0; i < NTASK * 3; i++) s += sv[i];
        out[0] = (float)(-s / (double)TOTPIX);
    }
}

// ---------------------------------------------------------------------------
extern "C" void kernel_launch(void* const* d_in, const int* in_sizes, int n_in,
                              void* d_out, int out_size) {
    (void)in_sizes; (void)n_in; (void)out_size;
    const float* preds = (const float*)d_in[0];
    float* out = (float*)d_out;

    cudaFuncSetAttribute(k_flood, cudaFuncAttributeMaxDynamicSharedMemorySize,
                         2 * 8192 * (int)sizeof(uint32_t));

    k_sample<<<(TOTPIX + 255) / 256, 256>>>(preds);
    {
        dim3 g(HH / 16, NTASK);
        k_seed<<<g, 256>>>();
    }
    k_flood<<<NTASK * 3, 128, 2 * 8192 * sizeof(uint32_t)>>>(preds);
    k_final<<<1, 128>>>(out);
}

// round 3
// speedup vs baseline: 1.3115x; 1.1117x over previous
#include <cuda_runtime.h>
#include <cstdint>

// ===========================================================================
// reinforce_cons_loss:
//   K1 Threefry-2x32 Gumbel-max categorical sampling (product-form argmax,
//      MUFU fast-log2 with exact near-tie fallback) + state reset
//   K2 5x5 fg-neighbor counts + per-(task,class) argmax seed (packed byte-SIMD)
//   K3 per-(task,class) 8-connectivity flood fill (bitset row closure)
//      + component log-prob sum + last-CTA final loss reduction
// ===========================================================================

#define NIMG   4
#define NSAMP  10
#define HH     512
#define WW     512
#define NTASK  (NIMG*NSAMP)            // 40 image-samples
#define NPIX   (HH*WW)                 // 262144 = 1<<18
#define TOTPIX ((unsigned)NTASK*NPIX)  // 10485760

__device__ uint8_t            g_cls[(size_t)NTASK * NPIX];
__device__ unsigned long long g_seed[NTASK * 3];
__device__ double             g_partial[NTASK * 3];
__device__ int                g_done;

// ---------------------------------------------------------------------------
// Threefry-2x32, 20 rounds, key (0,42), counter (0, idx); out = o0 ^ o1
// (jax_threefry_partitionable — verified rounds 1-2, rel_err 6e-8)
// ---------------------------------------------------------------------------
#define TF_ROUND(x0,x1,R) { x0 += x1; x1 = __funnelshift_l(x1, x1, (R)); x1 ^= x0; }

__device__ __forceinline__ uint32_t gumbel_bits(uint32_t idx) {
    const uint32_t k0 = 0u, k1 = 42u;
    const uint32_t k2 = k0 ^ k1 ^ 0x1BD11BDAu;
    uint32_t x0 = k0, x1 = idx + k1;
    TF_ROUND(x0,x1,13) TF_ROUND(x0,x1,15) TF_ROUND(x0,x1,26) TF_ROUND(x0,x1,6)
    x0 += k1; x1 += k2 + 1u;
    TF_ROUND(x0,x1,17) TF_ROUND(x0,x1,29) TF_ROUND(x0,x1,16) TF_ROUND(x0,x1,24)
    x0 += k2; x1 += k0 + 2u;
    TF_ROUND(x0,x1,13) TF_ROUND(x0,x1,15) TF_ROUND(x0,x1,26) TF_ROUND(x0,x1,6)
    x0 += k0; x1 += k1 + 3u;
    TF_ROUND(x0,x1,17) TF_ROUND(x0,x1,29) TF_ROUND(x0,x1,16) TF_ROUND(x0,x1,24)
    x0 += k1; x1 += k2 + 4u;
    TF_ROUND(x0,x1,13) TF_ROUND(x0,x1,15) TF_ROUND(x0,x1,26) TF_ROUND(x0,x1,6)
    x0 += k2; x1 += k0 + 5u;
    return x0 ^ x1;
}

// ---------------------------------------------------------------------------
// K1: gumbel-max, product form: argmax_c p_c / (-log2 u_c).
//   Fast path uses MUFU __log2f (abs err <= ~3.5e-7 on the log2 value), so a
//   cross-product comparison p_i*w_j vs p_j*w_i can only flip when
//   |lhs-rhs| <= |p_i d_j| + |p_j d_i| + rounding <= 7e-7 + ~1e-7*(lhs+rhs).
//   Any comparison inside the superset threshold 2e-6 + 2e-6*(lhs+rhs) is
//   re-evaluated with precise log2f -> argmax identical to the verified
//   precise path for every pixel.
// ---------------------------------------------------------------------------
__global__ void __launch_bounds__(256) k_sample(const float* __restrict__ preds) {
    unsigned gid = blockIdx.x * 256u + threadIdx.x;
    if (blockIdx.x == 0) {
        if (threadIdx.x < NTASK * 3) g_seed[threadIdx.x] = 0ull;
        if (threadIdx.x == 0) g_done = 0;
    }
    if (gid >= TOTPIX) return;
    unsigned hw = gid & 0x3FFFFu;
    unsigned n  = (gid >> 18) & 3u;
    const float* pb = preds + ((size_t)n << 20) + hw;   // preds[n][c][h][w]
    unsigned base = gid << 2;

    float p0 = pb[0];
    float p1 = pb[(size_t)1 << 18];
    float p2 = pb[(size_t)2 << 18];
    float p3 = pb[(size_t)3 << 18];

    const float tiny = 1.17549435082228751e-38f;
    uint32_t b0 = gumbel_bits(base + 0);
    uint32_t b1 = gumbel_bits(base + 1);
    uint32_t b2 = gumbel_bits(base + 2);
    uint32_t b3 = gumbel_bits(base + 3);
    float u0 = fmaxf(__uint_as_float((b0 >> 9) | 0x3f800000u) - 1.0f, tiny);
    float u1 = fmaxf(__uint_as_float((b1 >> 9) | 0x3f800000u) - 1.0f, tiny);
    float u2 = fmaxf(__uint_as_float((b2 >> 9) | 0x3f800000u) - 1.0f, tiny);
    float u3 = fmaxf(__uint_as_float((b3 >> 9) | 0x3f800000u) - 1.0f, tiny);

    // fast path (MUFU.LG2)
    float w0 = -__log2f(u0);
    float w1 = -__log2f(u1);
    float w2 = -__log2f(u2);
    float w3 = -__log2f(u3);

    float bp = p0, bw = w0; unsigned bc = 0;
    bool risky = false;
    {
        float lhs = p1 * bw, rhs = bp * w1;
        risky |= fabsf(lhs - rhs) <= 2e-6f + 2e-6f * (lhs + rhs);
        if (lhs > rhs) { bp = p1; bw = w1; bc = 1; }
    }
    {
        float lhs = p2 * bw, rhs = bp * w2;
        risky |= fabsf(lhs - rhs) <= 2e-6f + 2e-6f * (lhs + rhs);
        if (lhs > rhs) { bp = p2; bw = w2; bc = 2; }
    }
    {
        float lhs = p3 * bw, rhs = bp * w3;
        risky |= fabsf(lhs - rhs) <= 2e-6f + 2e-6f * (lhs + rhs);
        if (lhs > rhs) { bp = p3; bw = w3; bc = 3; }
    }
    if (risky) {           // ~1e-5 of pixels: redo with precise log2f
        w0 = -log2f(u0);
        w1 = -log2f(u1);
        w2 = -log2f(u2);
        w3 = -log2f(u3);
        bp = p0; bw = w0; bc = 0;
        if (p1 * bw > bp * w1) { bp = p1; bw = w1; bc = 1; }
        if (p2 * bw > bp * w2) { bp = p2; bw = w2; bc = 2; }
        if (p3 * bw > bp * w3) { bp = p3; bw = w3; bc = 3; }
    }
    g_cls[gid] = (uint8_t)bc;
}

// ---------------------------------------------------------------------------
// K2: per task t (40) and 16-row block (32): 5x5 box counts of each class,
//     packed one class per byte lane of a u32 (counts <= 25). For each fg
//     pixel, candidate key = (count<<18) | (0x3FFFF - flat_idx); global
//     atomicMax => max count, lowest flat index on ties.
// ---------------------------------------------------------------------------
__global__ void __launch_bounds__(256) k_seed() {
    __shared__ uint32_t           scls[20][128];
    __shared__ uint32_t           svs[16][512];
    __shared__ unsigned long long sbest[3];

    int tid = threadIdx.x;
    int t   = blockIdx.y;
    int r0  = blockIdx.x * 16;
    const uint32_t* cls32 = (const uint32_t*)g_cls + (size_t)t * (NPIX/4);

    for (int i = tid; i < 20 * 128; i += 256) {
        int row = i >> 7, wd = i & 127;
        int rr = r0 - 2 + row;
        scls[row][wd] = (rr >= 0 && rr < HH) ? cls32[rr * 128 + wd] : 0u;
    }
    if (tid < 3) sbest[tid] = 0ull;
    __syncthreads();

    for (int x = tid; x < 512; x += 256) {
        int wd = x >> 2, sh = (x & 3) * 8;
        uint32_t w = 0;
#pragma unroll
        for (int k = 0; k < 5; k++) {
            uint32_t b = (scls[k][wd] >> sh) & 0xFFu;
            w += 1u << (b << 3);
        }
        svs[0][x] = w;
        for (int y = 1; y < 16; y++) {
            uint32_t ba = (scls[y + 4][wd] >> sh) & 0xFFu;
            uint32_t bs = (scls[y - 1][wd] >> sh) & 0xFFu;
            w += (1u << (ba << 3)) - (1u << (bs << 3));
            svs[y][x] = w;
        }
    }
    __syncthreads();

    unsigned long long lbest0 = 0, lbest1 = 0, lbest2 = 0;
    for (int i = tid; i < 16 * 512; i += 256) {
        int y = i >> 9, x = i & 511;
        uint32_t c0 = (scls[y + 2][x >> 2] >> ((x & 3) * 8)) & 0xFFu;
        if (c0 == 0u) continue;
        uint32_t h = svs[y][x];
        if (x >= 1)   h += svs[y][x - 1];
        if (x >= 2)   h += svs[y][x - 2];
        if (x <= 510) h += svs[y][x + 1];
        if (x <= 509) h += svs[y][x + 2];
        uint32_t cnt = (h >> (c0 << 3)) & 0xFFu;
        unsigned idx = ((unsigned)(r0 + y) << 9) | (unsigned)x;
        unsigned long long key =
            ((unsigned long long)cnt << 18) | (unsigned long long)(0x3FFFFu - idx);
        if (c0 == 1u)      { if (key > lbest0) lbest0 = key; }
        else if (c0 == 2u) { if (key > lbest1) lbest1 = key; }
        else               { if (key > lbest2) lbest2 = key; }
    }
    if (lbest0) atomicMax(&sbest[0], lbest0);
    if (lbest1) atomicMax(&sbest[1], lbest1);
    if (lbest2) atomicMax(&sbest[2], lbest2);
    __syncthreads();
    if (tid < 3 && sbest[tid]) atomicMax(&g_seed[t * 3 + tid], sbest[tid]);
}

// ---------------------------------------------------------------------------
// K3: one CTA (128 thr) per (task, class). Bitset flood fill with full
//     horizontal row closure per iteration; 1 barrier/iter via 3-slot flag.
//     Then component log-prob sum over bbox rows, and the LAST finishing CTA
//     performs the final loss reduction (fixed tree -> deterministic).
// ---------------------------------------------------------------------------
__device__ __forceinline__ uint32_t word_closure(uint32_t g, uint32_t s) {
    uint32_t up = g & ~(g + s);
    uint32_t gr = __brev(g), sr = __brev(s);
    uint32_t dn = __brev(gr & ~(gr + sr));
    return s | up | dn;
}

__global__ void __launch_bounds__(128) k_flood(const float* __restrict__ preds,
                                               float* __restrict__ out) {
    extern __shared__ uint32_t sm[];
    uint32_t* fg = sm;          // 8192 words
    uint32_t* fl = sm + 8192;   // 8192 words
    __shared__ int s_r0, s_r1;
    __shared__ int s_flag[3];
    __shared__ double s_red[4];
    __shared__ int s_last;

    int tid  = threadIdx.x;
    int task = blockIdx.x;
    int t = task / 3;
    int c = task % 3 + 1;
    int n = t & 3;

    unsigned long long key = g_seed[task];
    double acc = 0.0;
    bool empty = ((key >> 18) == 0ull);

    if (!empty) {
        // build fg bitset for class c
        const uint32_t* cls32 = (const uint32_t*)g_cls + (size_t)t * (NPIX/4);
        uint32_t cpat = (uint32_t)c * 0x01010101u;
        for (int w = tid; w < 8192; w += 128) {
            uint32_t bits = 0;
#pragma unroll
            for (int k = 0; k < 8; k++) {
                uint32_t v  = cls32[w * 8 + k];
                uint32_t eq = __vcmpeq4(v, cpat);
                uint32_t nb = ((eq & 0x01010101u) * 0x01020408u) >> 24;
                bits |= (nb & 0xFu) << (k * 4);
            }
            fg[w] = bits;
            fl[w] = 0u;
        }
        if (tid == 0) {
            int sidx = 0x3FFFF - (int)(key & 0x3FFFFull);
            s_r0 = sidx >> 9; s_r1 = sidx >> 9;
            s_flag[0] = 0; s_flag[1] = 0; s_flag[2] = 0;
        }
        __syncthreads();
        if (tid == 0) {
            int sidx = 0x3FFFF - (int)(key & 0x3FFFFull);
            int sr = sidx >> 9, sc = sidx & 511;
            fl[sr * 16 + (sc >> 5)] = 1u << (sc & 31);
        }
        __syncthreads();

        for (int iter = 0; ; iter++) {
            int p = iter % 3;
            int r0 = s_r0 > 0   ? s_r0 - 1 : 0;
            int r1 = s_r1 < 511 ? s_r1 + 1 : 511;
            int ch = 0, myr0 = 1 << 30, myr1 = -1;
            for (int r = r0 + tid; r <= r1; r += 128) {
                uint32_t* F = fl + r * 16;
                const uint32_t* G = fg + r * 16;
                bool hU = (r > 0), hD = (r < 511);
                const uint32_t* U = fl + (r - 1) * 16;
                const uint32_t* D = fl + (r + 1) * 16;
                uint32_t S[16], Gw[16], Fo[16];
                uint32_t Vp = 0;
                uint32_t Vc = (hU ? U[0] : 0u) | (hD ? D[0] : 0u);
#pragma unroll
                for (int j = 0; j < 16; j++) {
                    uint32_t Vn = (j < 15)
                        ? ((hU ? U[j+1] : 0u) | (hD ? D[j+1] : 0u)) : 0u;
                    Gw[j] = G[j];
                    Fo[j] = F[j];
                    uint32_t vd = Vc | (Vc << 1) | (Vp >> 31) | (Vc >> 1) | (Vn << 31);
                    S[j] = Fo[j] | (vd & Gw[j]);
                    Vp = Vc; Vc = Vn;
                }
                uint32_t carry = 0;
#pragma unroll
                for (int j = 0; j < 16; j++) {
                    uint32_t s = S[j] | (carry & Gw[j] & 1u);
                    uint32_t cl = word_closure(Gw[j], s);
                    S[j] = cl; carry = cl >> 31;
                }
                carry = 0;
                uint32_t diff = 0;
#pragma unroll
                for (int j = 15; j >= 0; j--) {
                    uint32_t s = S[j] | ((0u - carry) & Gw[j] & 0x80000000u);
                    uint32_t cl = word_closure(Gw[j], s);
                    S[j] = cl; carry = cl & 1u;
                    diff |= cl ^ Fo[j];
                }
                if (diff) {
#pragma unroll
                    for (int j = 0; j < 16; j++) F[j] = S[j];
                    ch = 1; if (r < myr0) myr0 = r; if (r > myr1) myr1 = r;
                }
            }
            if (ch) {
                s_flag[p] = 1;
                atomicMin(&s_r0, myr0);
                atomicMax(&s_r1, myr1);
            }
            if (tid == 0) s_flag[(p + 1) % 3] = 0;
            __syncthreads();
            if (!s_flag[p]) break;
        }

        // sum log(prob + eps) over component pixels (bbox rows only)
        const float* pb = preds + ((size_t)(n * 4 + c) << 18);
        int w0 = s_r0 * 16, w1 = (s_r1 + 1) * 16;
        for (int w = w0 + tid; w < w1; w += 128) {
            uint32_t m = fl[w];
            int rowbase = (w >> 4) << 9;
            int colbase = (w & 15) << 5;
            while (m) {
                int b = __ffs(m) - 1;
                m &= m - 1;
                float p = pb[rowbase + colbase + b];
                acc += (double)logf(p + 1e-16f);
            }
        }
    }

    // per-CTA reduction (fixed tree)
#pragma unroll
    for (int off = 16; off; off >>= 1)
        acc += __shfl_down_sync(0xFFFFFFFFu, acc, off);
    if ((tid & 31) == 0) s_red[tid >> 5] = acc;
    __syncthreads();
    if (tid == 0) {
        double tt = s_red[0] + s_red[1] + s_red[2] + s_red[3];
        g_partial[task] = tt;
        __threadfence();
        int old = atomicAdd(&g_done, 1);
        s_last = (old == NTASK * 3 - 1);
    }
    __syncthreads();

    if (s_last) {
        __threadfence();   // acquire all g_partial writes
        double v = (tid < NTASK * 3) ? g_partial[tid] : 0.0;
#pragma unroll
        for (int off = 16; off; off >>= 1)
            v += __shfl_down_sync(0xFFFFFFFFu, v, off);
        if ((tid & 31) == 0) s_red[tid >> 5] = v;
        __syncthreads();
        if (tid == 0) {
            double s = s_red[0] + s_red[1] + s_red[2] + s_red[3];
            out[0] = (float)(-s / (double)TOTPIX);
        }
    }
}

// ---------------------------------------------------------------------------
extern "C" void kernel_launch(void* const* d_in, const int* in_sizes, int n_in,
                              void* d_out, int out_size) {
    (void)in_sizes; (void)n_in; (void)out_size;
    const float* preds = (const float*)d_in[0];
    float* out = (float*)d_out;

    cudaFuncSetAttribute(k_flood, cudaFuncAttributeMaxDynamicSharedMemorySize,
                         2 * 8192 * (int)sizeof(uint32_t));

    k_sample<<<(TOTPIX + 255) / 256, 256>>>(preds);
    {
        dim3 g(HH / 16, NTASK);
        k_seed<<<g, 256>>>();
    }
    k_flood<<<NTASK * 3, 128, 2 * 8192 * sizeof(uint32_t)>>>(preds, out);
}